// round 3
// baseline (speedup 1.0000x reference)
#include <cuda_runtime.h>
#include <math.h>

#define TT 512
#define BB 64
#define DH 1024
#define BH (BB*DH)
#define NB 128          // persistent blocks (1 per SM, all co-resident)
#define CPB 8           // hidden columns per block: 128*8 = 1024
#define WSTRIDE 2052    // floats per col-pair weight slab (pad: 2052 mod 32 = 4)

// ---------------- scratch (device globals: no runtime allocation) ----------
__device__ float g_Xr[(size_t)TT * BH];
__device__ float g_Xz[(size_t)TT * BH];
__device__ float g_Xh[(size_t)TT * BH];
__device__ float g_h[2][BH];
__device__ float g_Rh[BH];
__device__ unsigned g_bar_count = 0;
__device__ volatile unsigned g_bar_gen = 0;

// ---------------- software grid barrier (all NB blocks resident) ----------
__device__ __forceinline__ void gridBarrier() {
    __syncthreads();
    if (threadIdx.x == 0) {
        __threadfence();
        unsigned g = g_bar_gen;
        if (atomicAdd(&g_bar_count, 1u) == (unsigned)(NB - 1)) {
            g_bar_count = 0;
            __threadfence();
            g_bar_gen = g + 1;
        } else {
            while (g_bar_gen == g) { __nanosleep(32); }
        }
        __threadfence();
    }
    __syncthreads();
}

// ---------------- input projection GEMM: [T*B,1024] x [1024,1024] ---------
__global__ void __launch_bounds__(256) input_gemm(
    const float* __restrict__ X,
    const float* __restrict__ Wr, const float* __restrict__ Wz, const float* __restrict__ Wh,
    const float* __restrict__ br, const float* __restrict__ bz, const float* __restrict__ bh)
{
    const float* W; const float* bias; float* Out;
    if (blockIdx.z == 0)      { W = Wr; bias = br; Out = g_Xr; }
    else if (blockIdx.z == 1) { W = Wz; bias = bz; Out = g_Xz; }
    else                      { W = Wh; bias = bh; Out = g_Xh; }

    __shared__ float As[16][65];   // A^T tile (k, row), padded
    __shared__ float Bs[16][64];   // B tile (k, col)

    const int tid = threadIdx.x;
    const int rowBase = blockIdx.y * 64;
    const int colBase = blockIdx.x * 64;
    const int tx = tid & 15, ty = tid >> 4;

    const int arow = tid >> 2;          // 0..63
    const int akq  = (tid & 3) * 4;     // 0,4,8,12
    const int bk   = tid >> 4;          // 0..15
    const int bc   = (tid & 15) * 4;    // 0..60

    float acc[4][4] = {};

    for (int k0 = 0; k0 < 1024; k0 += 16) {
        float4 av = *(const float4*)(X + (size_t)(rowBase + arow) * 1024 + k0 + akq);
        As[akq + 0][arow] = av.x;
        As[akq + 1][arow] = av.y;
        As[akq + 2][arow] = av.z;
        As[akq + 3][arow] = av.w;
        *(float4*)&Bs[bk][bc] =
            *(const float4*)(W + (size_t)(k0 + bk) * 1024 + colBase + bc);
        __syncthreads();
        #pragma unroll
        for (int kk = 0; kk < 16; kk++) {
            float a0 = As[kk][ty * 4 + 0];
            float a1 = As[kk][ty * 4 + 1];
            float a2 = As[kk][ty * 4 + 2];
            float a3 = As[kk][ty * 4 + 3];
            float4 b = *(float4*)&Bs[kk][tx * 4];
            acc[0][0] += a0 * b.x; acc[0][1] += a0 * b.y; acc[0][2] += a0 * b.z; acc[0][3] += a0 * b.w;
            acc[1][0] += a1 * b.x; acc[1][1] += a1 * b.y; acc[1][2] += a1 * b.z; acc[1][3] += a1 * b.w;
            acc[2][0] += a2 * b.x; acc[2][1] += a2 * b.y; acc[2][2] += a2 * b.z; acc[2][3] += a2 * b.w;
            acc[3][0] += a3 * b.x; acc[3][1] += a3 * b.y; acc[3][2] += a3 * b.z; acc[3][3] += a3 * b.w;
        }
        __syncthreads();
    }

    float4 bv = *(const float4*)(bias + colBase + tx * 4);
    #pragma unroll
    for (int i = 0; i < 4; i++) {
        float4 o;
        o.x = acc[i][0] + bv.x;
        o.y = acc[i][1] + bv.y;
        o.z = acc[i][2] + bv.z;
        o.w = acc[i][3] + bv.w;
        *(float4*)(Out + (size_t)(rowBase + ty * 4 + i) * 1024 + colBase + tx * 4) = o;
    }
}

// ---------------- persistent recurrent kernel -----------------------------
// 128 blocks x 256 threads. Block b owns hidden columns [8b, 8b+8).
// Weight slices live in SMEM for all 512 steps, packed [col-pair][k][2]
// so one float4 fetches 2k x 2cols.
// Thread map: r = tid>>2 (batch row 0..63), cp = tid&3 (col pair), c0 = cp*2.
__device__ __forceinline__ float sigmoidf_(float x) {
    return 1.0f / (1.0f + expf(-x));
}

__global__ void __launch_bounds__(256) gru_recurrent(
    const float* __restrict__ state,
    const float* __restrict__ Whr, const float* __restrict__ Whz, const float* __restrict__ Whh,
    float* __restrict__ out)
{
    extern __shared__ float smem[];
    float* wr_s = smem;                    // 4 * WSTRIDE
    float* wz_s = smem + 4 * WSTRIDE;      // 4 * WSTRIDE
    float* wh_s = smem + 8 * WSTRIDE;      // 4 * WSTRIDE
    float* stg  = smem + 12 * WSTRIDE;     // 64 rows * 132 staging

    const int tid = threadIdx.x;
    const int bid = blockIdx.x;
    const int cB  = bid * CPB;

    // load persistent W slices, packed [cp][k*2 + ci]
    for (int i = tid; i < 1024 * CPB; i += 256) {
        int k = i >> 3, c = i & 7;
        int di = (c >> 1) * WSTRIDE + k * 2 + (c & 1);
        size_t gi = (size_t)k * 1024 + cB + c;
        wr_s[di] = Whr[gi];
        wz_s[di] = Whz[gi];
        wh_s[di] = Whh[gi];
    }
    // init h[0] = state
    for (int i = bid * 256 + tid; i < BH; i += NB * 256)
        g_h[0][i] = state[i];
    gridBarrier();

    const int r   = tid >> 2;            // 0..63
    const int cp  = tid & 3;             // col pair 0..3
    const int col = cB + cp * 2;
    const float* hp = &stg[r * 132];
    const float* wrB = wr_s + cp * WSTRIDE;
    const float* wzB = wz_s + cp * WSTRIDE;
    const float* whB = wh_s + cp * WSTRIDE;

    for (int t = 0; t < TT; t++) {
        const float* hcur = g_h[t & 1];
        float*       hnxt = g_h[(t & 1) ^ 1];

        // ---- phase 1: R = sig(Xr + h Whr), Z = sig(Xz + h Whz) ----
        float ar0 = 0.f, ar1 = 0.f, az0 = 0.f, az1 = 0.f;
        for (int kc = 0; kc < 1024; kc += 128) {
            __syncthreads();
            for (int i = tid; i < 2048; i += 256) {
                int rr = i >> 5, cc = (i & 31) * 4;
                *(float4*)&stg[rr * 132 + cc] =
                    __ldcg((const float4*)(hcur + rr * 1024 + kc + cc));
            }
            __syncthreads();
            const float* wrp = wrB + kc * 2;
            const float* wzp = wzB + kc * 2;
            #pragma unroll 8
            for (int kk = 0; kk < 128; kk += 2) {
                float2 a  = *(const float2*)(hp + kk);
                float4 wr = *(const float4*)(wrp + kk * 2);  // [k][c0],[k][c0+1],[k+1][c0],[k+1][c0+1]
                float4 wz = *(const float4*)(wzp + kk * 2);
                ar0 += a.x * wr.x + a.y * wr.z;
                ar1 += a.x * wr.y + a.y * wr.w;
                az0 += a.x * wz.x + a.y * wz.z;
                az1 += a.x * wz.y + a.y * wz.w;
            }
        }
        size_t xoff = (size_t)t * BH + (size_t)r * 1024 + col;
        float2 xr = __ldg((const float2*)(g_Xr + xoff));
        float2 xz = __ldg((const float2*)(g_Xz + xoff));
        float rv0 = sigmoidf_(xr.x + ar0);
        float rv1 = sigmoidf_(xr.y + ar1);
        float zv0 = sigmoidf_(xz.x + az0);
        float zv1 = sigmoidf_(xz.y + az1);
        float2 hv = __ldcg((const float2*)(hcur + (size_t)r * 1024 + col));
        float2 rh; rh.x = rv0 * hv.x; rh.y = rv1 * hv.y;
        __stcg((float2*)(g_Rh + (size_t)r * 1024 + col), rh);
        gridBarrier();

        // ---- phase 2: H_hat = tanh(Xh + (R.h) Whh); h' = Z h + (1-Z) H_hat ----
        float ah0 = 0.f, ah1 = 0.f;
        for (int kc = 0; kc < 1024; kc += 128) {
            __syncthreads();
            for (int i = tid; i < 2048; i += 256) {
                int rr = i >> 5, cc = (i & 31) * 4;
                *(float4*)&stg[rr * 132 + cc] =
                    __ldcg((const float4*)(g_Rh + rr * 1024 + kc + cc));
            }
            __syncthreads();
            const float* whp = whB + kc * 2;
            #pragma unroll 8
            for (int kk = 0; kk < 128; kk += 2) {
                float2 a  = *(const float2*)(hp + kk);
                float4 wh = *(const float4*)(whp + kk * 2);
                ah0 += a.x * wh.x + a.y * wh.z;
                ah1 += a.x * wh.y + a.y * wh.w;
            }
        }
        float2 xh = __ldg((const float2*)(g_Xh + xoff));
        float hh0 = tanhf(xh.x + ah0);
        float hh1 = tanhf(xh.y + ah1);
        float2 hn;
        hn.x = zv0 * hv.x + (1.0f - zv0) * hh0;
        hn.y = zv1 * hv.y + (1.0f - zv1) * hh1;
        __stcg((float2*)(hnxt + (size_t)r * 1024 + col), hn);
        *(float2*)(out + xoff) = hn;
        if (t == TT - 1)
            *(float2*)(out + (size_t)TT * BH + (size_t)r * 1024 + col) = hn;
        gridBarrier();
    }
}

// ---------------- launch ---------------------------------------------------
extern "C" void kernel_launch(void* const* d_in, const int* in_sizes, int n_in,
                              void* d_out, int out_size) {
    const float* X    = (const float*)d_in[0];
    const float* state= (const float*)d_in[1];
    const float* W_xr = (const float*)d_in[2];
    const float* W_hr = (const float*)d_in[3];
    const float* b_r  = (const float*)d_in[4];
    const float* W_xz = (const float*)d_in[5];
    const float* W_hz = (const float*)d_in[6];
    const float* b_z  = (const float*)d_in[7];
    const float* W_xh = (const float*)d_in[8];
    const float* W_hh = (const float*)d_in[9];
    const float* b_h  = (const float*)d_in[10];
    float* out = (float*)d_out;

    dim3 g1(16, 512, 3);   // N-tiles, M-tiles, 3 weight sets
    input_gemm<<<g1, 256>>>(X, W_xr, W_xz, W_xh, b_r, b_z, b_h);

    const int smem_bytes = (12 * WSTRIDE + 64 * 132) * (int)sizeof(float); // 132,288 B
    cudaFuncSetAttribute(gru_recurrent,
                         cudaFuncAttributeMaxDynamicSharedMemorySize, smem_bytes);
    gru_recurrent<<<NB, 256, smem_bytes>>>(state, W_hr, W_hz, W_hh, out);
}

// round 5
// speedup vs baseline: 3.2718x; 3.2718x over previous
#include <cuda_runtime.h>
#include <cuda_bf16.h>
#include <math.h>
#include <stdint.h>

#define TT 512
#define BB 64
#define DH 1024
#define BH (BB*DH)
#define NB 128          // persistent blocks, 1/SM
#define CPB 8           // hidden columns per block

// ---------------- recurrent kernel SMEM layout (bytes) --------------------
#define RS_W    0          // 6 slabs x 16384: WRhi,WRlo,WZhi,WZlo,WHhi,WHlo
#define RS_AHI  98304      // A staging hi: 64 rows x 528B
#define RS_ALO  132096
#define RS_Z    165888     // zbuf 64x8 f32
#define RS_TOT  167936
#define ASTRIDE 528        // 256 bf16 (512B) + 16B pad

// ---------------- input gemm SMEM layout (bytes) --------------------------
#define IS_AHI  0          // 128 rows x 144B
#define IS_ALO  18432
#define IS_WHI  36864      // 64 rows x 528B
#define IS_WLO  70656
#define IS_TOT  104448
#define IA_STR  144
#define IW_STR  528

// ---------------- device globals ------------------------------------------
__device__ float g_Xr[(size_t)TT * BH];
__device__ float g_Xz[(size_t)TT * BH];
__device__ float g_Xh[(size_t)TT * BH];
__device__ float g_h_f32[BH];
__device__ __nv_bfloat16 g_h_hi[BH], g_h_lo[BH];
__device__ __nv_bfloat16 g_Rh_hi[BH], g_Rh_lo[BH];
__device__ unsigned g_bar_count = 0;
__device__ volatile unsigned g_bar_gen = 0;

// ---------------- helpers -------------------------------------------------
__device__ __forceinline__ uint32_t smem_u32(const void* p) {
    uint32_t a;
    asm("{ .reg .u64 t; cvta.to.shared.u64 t, %1; cvt.u32.u64 %0, t; }" : "=r"(a) : "l"(p));
    return a;
}
__device__ __forceinline__ void mma16816(float* c, const uint32_t* a, const uint32_t* b) {
    asm volatile("mma.sync.aligned.m16n8k16.row.col.f32.bf16.bf16.f32 "
        "{%0,%1,%2,%3}, {%4,%5,%6,%7}, {%8,%9}, {%0,%1,%2,%3};"
        : "+f"(c[0]), "+f"(c[1]), "+f"(c[2]), "+f"(c[3])
        : "r"(a[0]), "r"(a[1]), "r"(a[2]), "r"(a[3]), "r"(b[0]), "r"(b[1]));
}
__device__ __forceinline__ void ldsm_x4(uint32_t* r, uint32_t a) {
    asm volatile("ldmatrix.sync.aligned.m8n8.x4.shared.b16 {%0,%1,%2,%3}, [%4];"
        : "=r"(r[0]), "=r"(r[1]), "=r"(r[2]), "=r"(r[3]) : "r"(a));
}
__device__ __forceinline__ void ldsm_x2t(uint32_t* r, uint32_t a) {
    asm volatile("ldmatrix.sync.aligned.m8n8.x2.trans.shared.b16 {%0,%1}, [%2];"
        : "=r"(r[0]), "=r"(r[1]) : "r"(a));
}
__device__ __forceinline__ void ldsm_x4t(uint32_t* r, uint32_t a) {
    asm volatile("ldmatrix.sync.aligned.m8n8.x4.trans.shared.b16 {%0,%1,%2,%3}, [%4];"
        : "=r"(r[0]), "=r"(r[1]), "=r"(r[2]), "=r"(r[3]) : "r"(a));
}
__device__ __forceinline__ uint32_t packbf(__nv_bfloat16 x, __nv_bfloat16 y) {
    unsigned short ux = *(unsigned short*)&x, uy = *(unsigned short*)&y;
    return (uint32_t)ux | ((uint32_t)uy << 16);
}
// split v into hi/lo bf16 pair
__device__ __forceinline__ void split2(float vx, float vy, uint32_t& hi, uint32_t& lo) {
    __nv_bfloat16 hx = __float2bfloat16(vx), hy = __float2bfloat16(vy);
    __nv_bfloat16 lx = __float2bfloat16(vx - __bfloat162float(hx));
    __nv_bfloat16 ly = __float2bfloat16(vy - __bfloat162float(hy));
    hi = packbf(hx, hy); lo = packbf(lx, ly);
}
__device__ __forceinline__ float sigf(float x) { return 1.0f / (1.0f + expf(-x)); }

// ---------------- grid barrier --------------------------------------------
__device__ __forceinline__ void gridBarrier() {
    __syncthreads();
    if (threadIdx.x == 0) {
        __threadfence();
        unsigned g = g_bar_gen;
        if (atomicAdd(&g_bar_count, 1u) == (unsigned)(NB - 1)) {
            g_bar_count = 0;
            __threadfence();
            g_bar_gen = g + 1;
        } else {
            while (g_bar_gen == g) { __nanosleep(20); }
        }
        __threadfence();
    }
    __syncthreads();
}

// ---------------- input projection GEMM (HMMA bf16 split) -----------------
// grid (4, 256, 3), 512 threads. Tile: M=128, N=256, K-chunk 64.
__global__ void __launch_bounds__(512, 1) input_gemm(
    const float* __restrict__ X,
    const float* __restrict__ Wr, const float* __restrict__ Wz, const float* __restrict__ Wh,
    const float* __restrict__ br, const float* __restrict__ bz, const float* __restrict__ bh)
{
    extern __shared__ char sm[];
    const uint32_t sb = smem_u32(sm);
    const float* W; const float* bias; float* Out;
    if (blockIdx.z == 0)      { W = Wr; bias = br; Out = g_Xr; }
    else if (blockIdx.z == 1) { W = Wz; bias = bz; Out = g_Xz; }
    else                      { W = Wh; bias = bh; Out = g_Xh; }

    const int tid = threadIdx.x;
    const int lane = tid & 31, w = tid >> 5;
    const int rowBase = blockIdx.y * 128;
    const int colBase = blockIdx.x * 256;
    const int mw = (w & 3) * 32;       // warp m-offset within tile
    const int nw = (w >> 2) * 64;      // warp n-offset within tile

    float acc[2][8][4];
    #pragma unroll
    for (int i = 0; i < 2; i++)
        #pragma unroll
        for (int j = 0; j < 8; j++)
            #pragma unroll
            for (int q = 0; q < 4; q++) acc[i][j][q] = 0.f;

    for (int k0 = 0; k0 < 1024; k0 += 64) {
        // ---- stage X tile 128x64 (convert fp32 -> bf16 hi/lo) ----
        #pragma unroll
        for (int it = 0; it < 4; it++) {
            int idx = tid + it * 512;          // 0..2047
            int r = idx >> 4, kq = (idx & 15) * 4;
            float4 v = __ldg((const float4*)(X + (size_t)(rowBase + r) * 1024 + k0 + kq));
            uint32_t h0, l0, h1, l1;
            split2(v.x, v.y, h0, l0);
            split2(v.z, v.w, h1, l1);
            char* pa = sm + IS_AHI + r * IA_STR + kq * 2;
            *(uint32_t*)(pa)     = h0; *(uint32_t*)(pa + 4) = h1;
            *(uint32_t*)(pa + (IS_ALO - IS_AHI))     = l0;
            *(uint32_t*)(pa + (IS_ALO - IS_AHI) + 4) = l1;
        }
        // ---- stage W tile 64x256 ----
        #pragma unroll
        for (int it = 0; it < 8; it++) {
            int idx = tid + it * 512;          // 0..4095
            int kk = idx >> 6, nq = (idx & 63) * 4;
            float4 v = __ldg((const float4*)(W + (size_t)(k0 + kk) * 1024 + colBase + nq));
            uint32_t h0, l0, h1, l1;
            split2(v.x, v.y, h0, l0);
            split2(v.z, v.w, h1, l1);
            char* pw = sm + IS_WHI + kk * IW_STR + nq * 2;
            *(uint32_t*)(pw)     = h0; *(uint32_t*)(pw + 4) = h1;
            *(uint32_t*)(pw + (IS_WLO - IS_WHI))     = l0;
            *(uint32_t*)(pw + (IS_WLO - IS_WHI) + 4) = l1;
        }
        __syncthreads();

        #pragma unroll
        for (int ks = 0; ks < 4; ks++) {
            uint32_t ah[2][4], al[2][4];
            #pragma unroll
            for (int i = 0; i < 2; i++) {
                uint32_t ab = sb + IS_AHI + (mw + i * 16 + (lane & 15)) * IA_STR
                            + ks * 32 + (lane >> 4) * 16;
                ldsm_x4(ah[i], ab);
                ldsm_x4(al[i], ab + (IS_ALO - IS_AHI));
            }
            #pragma unroll
            for (int jp = 0; jp < 4; jp++) {
                // trans x4: lanes0-15 -> rows k+(l&15) at n-group0; lanes16-31 at n-group+8
                uint32_t rrow = ks * 16 + (lane & 15);
                uint32_t ncol = nw + jp * 16 + (lane >> 4) * 8;
                uint32_t bb = sb + IS_WHI + rrow * IW_STR + ncol * 2;
                uint32_t bh[4], bl[4];
                ldsm_x4t(bh, bb);
                ldsm_x4t(bl, bb + (IS_WLO - IS_WHI));
                #pragma unroll
                for (int i = 0; i < 2; i++) {
                    mma16816(acc[i][jp*2+0], ah[i], &bh[0]);
                    mma16816(acc[i][jp*2+0], al[i], &bh[0]);
                    mma16816(acc[i][jp*2+0], ah[i], &bl[0]);
                    mma16816(acc[i][jp*2+1], ah[i], &bh[2]);
                    mma16816(acc[i][jp*2+1], al[i], &bh[2]);
                    mma16816(acc[i][jp*2+1], ah[i], &bl[2]);
                }
            }
        }
        __syncthreads();
    }

    // ---- epilogue: c0,c1 -> row g cols qn,qn+1 ; c2,c3 -> row g+8 ----
    const int g = lane >> 2, qn = (lane & 3) * 2;
    #pragma unroll
    for (int j = 0; j < 8; j++) {
        int col = colBase + nw + j * 8 + qn;
        float2 bv = *(const float2*)(bias + col);
        #pragma unroll
        for (int i = 0; i < 2; i++) {
            int r0 = rowBase + mw + i * 16 + g;
            float2 o0 = make_float2(acc[i][j][0] + bv.x, acc[i][j][1] + bv.y);
            float2 o1 = make_float2(acc[i][j][2] + bv.x, acc[i][j][3] + bv.y);
            *(float2*)(Out + (size_t)r0 * 1024 + col)       = o0;
            *(float2*)(Out + (size_t)(r0 + 8) * 1024 + col) = o1;
        }
    }
}

// ---------------- recurrent kernel (persistent, HMMA) ---------------------
__device__ __forceinline__ void stageA(char* sm,
        const __nv_bfloat16* __restrict__ hi, const __nv_bfloat16* __restrict__ lo,
        int kbase, int tid)
{
    #pragma unroll
    for (int it = 0; it < 8; it++) {
        int idx = tid + it * 256;          // 0..2047
        int r = idx >> 5, s = idx & 31;
        size_t go = (size_t)r * 1024 + kbase + s * 8;
        *(uint4*)(sm + RS_AHI + r * ASTRIDE + s * 16) = __ldcg((const uint4*)(hi + go));
        *(uint4*)(sm + RS_ALO + r * ASTRIDE + s * 16) = __ldcg((const uint4*)(lo + go));
    }
}

__global__ void __launch_bounds__(256, 1) gru_recurrent(
    const float* __restrict__ state,
    const float* __restrict__ Whr, const float* __restrict__ Whz, const float* __restrict__ Whh,
    float* __restrict__ out)
{
    extern __shared__ char sm[];
    const uint32_t sb = smem_u32(sm);
    const int tid = threadIdx.x;
    const int lane = tid & 31, w = tid >> 5;
    const int bid = blockIdx.x;
    const int cB  = bid * CPB;

    // ---- persistent W slabs: [k][8n] rows of 16B, hi/lo bf16 ----
    {
        const float* Wm[3] = { Whr, Whz, Whh };
        for (int idx = tid; idx < 8192; idx += 256) {
            int k = idx >> 3, n = idx & 7;
            #pragma unroll
            for (int m = 0; m < 3; m++) {
                float v = Wm[m][(size_t)k * 1024 + cB + n];
                __nv_bfloat16 h = __float2bfloat16(v);
                __nv_bfloat16 l = __float2bfloat16(v - __bfloat162float(h));
                *(__nv_bfloat16*)(sm + RS_W + (2*m)   * 16384 + k * 16 + n * 2) = h;
                *(__nv_bfloat16*)(sm + RS_W + (2*m+1) * 16384 + k * 16 + n * 2) = l;
            }
        }
    }
    // ---- init h ----
    for (int idx = tid; idx < 512; idx += 256) {
        int r = idx >> 3, n = idx & 7;
        size_t gi = (size_t)r * 1024 + cB + n;
        float v = state[gi];
        g_h_f32[gi] = v;
        __nv_bfloat16 h = __float2bfloat16(v);
        __nv_bfloat16 l = __float2bfloat16(v - __bfloat162float(h));
        g_h_hi[gi] = h; g_h_lo[gi] = l;
    }
    gridBarrier();

    const int m0  = (w & 3) * 16;
    const bool isR = (w < 4);
    const int g   = lane >> 2, qn = (lane & 3) * 2;
    const int r0  = m0 + g;
    const int col = cB + qn;
    const uint32_t wsel_hi = sb + RS_W + (isR ? 0 : 2) * 16384;
    const uint32_t whh_hi  = sb + RS_W + 4 * 16384;

    for (int t = 0; t < TT; t++) {
        // ================ phase 1: R (warps 0-3) / Z (warps 4-7) ==========
        float acc[4] = {0.f, 0.f, 0.f, 0.f};
        for (int c = 0; c < 4; c++) {
            stageA(sm, g_h_hi, g_h_lo, c * 256, tid);
            __syncthreads();
            uint32_t abase = sb + RS_AHI + (m0 + (lane & 15)) * ASTRIDE + (lane >> 4) * 16;
            uint32_t bbase = wsel_hi + (c * 256 + (lane & 15)) * 16;
            #pragma unroll
            for (int ks = 0; ks < 16; ks++) {
                uint32_t ah[4], al[4], bh[2], bl[2];
                ldsm_x4(ah, abase + ks * 32);
                ldsm_x4(al, abase + ks * 32 + (RS_ALO - RS_AHI));
                ldsm_x2t(bh, bbase + ks * 256);
                ldsm_x2t(bl, bbase + ks * 256 + 16384);
                mma16816(acc, ah, bh);
                mma16816(acc, al, bh);
                mma16816(acc, ah, bl);
            }
            __syncthreads();
        }
        // ---- epilogue 1 ----
        {
            size_t o0 = (size_t)t * BH + (size_t)r0 * 1024 + col;
            size_t o1 = o0 + 8 * 1024;
            size_t h0o = (size_t)r0 * 1024 + col, h1o = h0o + 8 * 1024;
            if (isR) {
                float2 xr0 = __ldg((const float2*)(g_Xr + o0));
                float2 xr1 = __ldg((const float2*)(g_Xr + o1));
                float2 h0 = *(const float2*)(g_h_f32 + h0o);
                float2 h1 = *(const float2*)(g_h_f32 + h1o);
                float a0 = sigf(xr0.x + acc[0]) * h0.x;
                float a1 = sigf(xr0.y + acc[1]) * h0.y;
                float a2 = sigf(xr1.x + acc[2]) * h1.x;
                float a3 = sigf(xr1.y + acc[3]) * h1.y;
                uint32_t hi, lo;
                split2(a0, a1, hi, lo);
                __stcg((uint32_t*)(g_Rh_hi + h0o), hi);
                __stcg((uint32_t*)(g_Rh_lo + h0o), lo);
                split2(a2, a3, hi, lo);
                __stcg((uint32_t*)(g_Rh_hi + h1o), hi);
                __stcg((uint32_t*)(g_Rh_lo + h1o), lo);
            } else {
                float2 xz0 = __ldg((const float2*)(g_Xz + o0));
                float2 xz1 = __ldg((const float2*)(g_Xz + o1));
                float2 z0 = make_float2(sigf(xz0.x + acc[0]), sigf(xz0.y + acc[1]));
                float2 z1 = make_float2(sigf(xz1.x + acc[2]), sigf(xz1.y + acc[3]));
                *(float2*)(sm + RS_Z + (r0 * 8 + qn) * 4)       = z0;
                *(float2*)(sm + RS_Z + ((r0 + 8) * 8 + qn) * 4) = z1;
            }
        }
        gridBarrier();

        // ================ phase 2: H_hat (warps 0-3 MMA) ==================
        float acch[4] = {0.f, 0.f, 0.f, 0.f};
        for (int c = 0; c < 4; c++) {
            stageA(sm, g_Rh_hi, g_Rh_lo, c * 256, tid);
            __syncthreads();
            if (w < 4) {
                uint32_t abase = sb + RS_AHI + (m0 + (lane & 15)) * ASTRIDE + (lane >> 4) * 16;
                uint32_t bbase = whh_hi + (c * 256 + (lane & 15)) * 16;
                #pragma unroll
                for (int ks = 0; ks < 16; ks++) {
                    uint32_t ah[4], al[4], bh[2], bl[2];
                    ldsm_x4(ah, abase + ks * 32);
                    ldsm_x4(al, abase + ks * 32 + (RS_ALO - RS_AHI));
                    ldsm_x2t(bh, bbase + ks * 256);
                    ldsm_x2t(bl, bbase + ks * 256 + 16384);
                    mma16816(acch, ah, bh);
                    mma16816(acch, al, bh);
                    mma16816(acch, ah, bl);
                }
            }
            __syncthreads();
        }
        // ---- epilogue 2 ----
        if (w < 4) {
            size_t o0 = (size_t)t * BH + (size_t)r0 * 1024 + col;
            size_t o1 = o0 + 8 * 1024;
            size_t h0o = (size_t)r0 * 1024 + col, h1o = h0o + 8 * 1024;
            float2 xh0 = __ldg((const float2*)(g_Xh + o0));
            float2 xh1 = __ldg((const float2*)(g_Xh + o1));
            float2 z0 = *(const float2*)(sm + RS_Z + (r0 * 8 + qn) * 4);
            float2 z1 = *(const float2*)(sm + RS_Z + ((r0 + 8) * 8 + qn) * 4);
            float2 h0 = *(const float2*)(g_h_f32 + h0o);
            float2 h1 = *(const float2*)(g_h_f32 + h1o);
            float hh0 = tanhf(xh0.x + acch[0]);
            float hh1 = tanhf(xh0.y + acch[1]);
            float hh2 = tanhf(xh1.x + acch[2]);
            float hh3 = tanhf(xh1.y + acch[3]);
            float n0 = z0.x * h0.x + (1.f - z0.x) * hh0;
            float n1 = z0.y * h0.y + (1.f - z0.y) * hh1;
            float n2 = z1.x * h1.x + (1.f - z1.x) * hh2;
            float n3 = z1.y * h1.y + (1.f - z1.y) * hh3;
            *(float2*)(out + o0) = make_float2(n0, n1);
            *(float2*)(out + o1) = make_float2(n2, n3);
            *(float2*)(g_h_f32 + h0o) = make_float2(n0, n1);
            *(float2*)(g_h_f32 + h1o) = make_float2(n2, n3);
            uint32_t hi, lo;
            split2(n0, n1, hi, lo);
            __stcg((uint32_t*)(g_h_hi + h0o), hi);
            __stcg((uint32_t*)(g_h_lo + h0o), lo);
            split2(n2, n3, hi, lo);
            __stcg((uint32_t*)(g_h_hi + h1o), hi);
            __stcg((uint32_t*)(g_h_lo + h1o), lo);
            if (t == TT - 1) {
                size_t f0 = (size_t)TT * BH + h0o;
                *(float2*)(out + f0)            = make_float2(n0, n1);
                *(float2*)(out + f0 + 8 * 1024) = make_float2(n2, n3);
            }
        }
        gridBarrier();
    }
}

// ---------------- launch ---------------------------------------------------
extern "C" void kernel_launch(void* const* d_in, const int* in_sizes, int n_in,
                              void* d_out, int out_size) {
    const float* X    = (const float*)d_in[0];
    const float* state= (const float*)d_in[1];
    const float* W_xr = (const float*)d_in[2];
    const float* W_hr = (const float*)d_in[3];
    const float* b_r  = (const float*)d_in[4];
    const float* W_xz = (const float*)d_in[5];
    const float* W_hz = (const float*)d_in[6];
    const float* b_z  = (const float*)d_in[7];
    const float* W_xh = (const float*)d_in[8];
    const float* W_hh = (const float*)d_in[9];
    const float* b_h  = (const float*)d_in[10];
    float* out = (float*)d_out;

    cudaFuncSetAttribute(input_gemm,
                         cudaFuncAttributeMaxDynamicSharedMemorySize, IS_TOT);
    dim3 g1(4, 256, 3);   // N-tiles(256), M-tiles(128), 3 weight sets
    input_gemm<<<g1, 512, IS_TOT>>>(X, W_xr, W_xz, W_xh, b_r, b_z, b_h);

    cudaFuncSetAttribute(gru_recurrent,
                         cudaFuncAttributeMaxDynamicSharedMemorySize, RS_TOT);
    gru_recurrent<<<NB, 256, RS_TOT>>>(state, W_hr, W_hz, W_hh, out);
}